// round 4
// baseline (speedup 1.0000x reference)
#include <cuda_runtime.h>

#define SEQ 12
#define DIM 10
#define H1 50
#define H2 10
#define TPB 256
#define ELEMS 4

// ---------- packed f32x2 helpers (sm_103a; ptxas never emits these from C++) ----------
__device__ __forceinline__ void fma2(float& dl, float& dh,
                                     float al, float ah,
                                     float bl, float bh,
                                     float cl, float ch) {
    asm("{\n\t.reg .b64 a,b,c,d;\n\t"
        "mov.b64 a,{%2,%3};\n\tmov.b64 b,{%4,%5};\n\tmov.b64 c,{%6,%7};\n\t"
        "fma.rn.f32x2 d,a,b,c;\n\t"
        "mov.b64 {%0,%1},d;\n\t}"
        : "=f"(dl), "=f"(dh)
        : "f"(al), "f"(ah), "f"(bl), "f"(bh), "f"(cl), "f"(ch));
}
__device__ __forceinline__ void mul2(float& dl, float& dh,
                                     float al, float ah, float bl, float bh) {
    asm("{\n\t.reg .b64 a,b,d;\n\t"
        "mov.b64 a,{%2,%3};\n\tmov.b64 b,{%4,%5};\n\t"
        "mul.rn.f32x2 d,a,b;\n\t"
        "mov.b64 {%0,%1},d;\n\t}"
        : "=f"(dl), "=f"(dh)
        : "f"(al), "f"(ah), "f"(bl), "f"(bh));
}
__device__ __forceinline__ void add2(float& dl, float& dh,
                                     float al, float ah, float bl, float bh) {
    asm("{\n\t.reg .b64 a,b,d;\n\t"
        "mov.b64 a,{%2,%3};\n\tmov.b64 b,{%4,%5};\n\t"
        "add.rn.f32x2 d,a,b;\n\t"
        "mov.b64 {%0,%1},d;\n\t}"
        : "=f"(dl), "=f"(dh)
        : "f"(al), "f"(ah), "f"(bl), "f"(bh));
}
__device__ __forceinline__ float ex2a(float x) {
    float r; asm("ex2.approx.f32 %0, %1;" : "=f"(r) : "f"(x)); return r;
}

// Derived-weight math (weight-only scalars precomputed per block):
//   scores[s] = k0*x_s + k1 ; k0 = A*t+Bc, k1 = C*t+Dc
//     A=We_w.Wt_w  Bc=We_w.Wt_b  C=We_b.Wt_w  Dc=We_b.Wt_b
//   p = scores/max(scores) ; attn = softmax_s(p) ; E = sum exp
//   u = (sum_s exp_s*x_s)/E          (ctx = We_w*u + We_b, sum(attn)=1)
//   h1_j = relu(P_j*t + Q_j*u + R_j)
//     P_j=W1[j,0:10].Wt_w  Q_j=W1[j,10:20].We_w
//     R_j=W1[j,0:10].Wt_b + W1[j,10:20].We_b + W1_b[j]
//   tm = W3.relu(W2.h1 + W2_b) + W3_b
//   mask_s = attn_s > mean(attn)  <=>  12*exp_s > E   (E > 0)

// Softmax/attention phase for one packed pair (bl, bh). Writes mask, returns
// t and u for both halves. Register arrays here die before the caller's hot loop.
__device__ __forceinline__ void attn_phase(
    const float* __restrict__ inputs, const float* __restrict__ targets,
    float* __restrict__ out, int B, int write_mask,
    int bl, int bh, bool hiv,
    float A, float Bc, float Cc, float Dc,
    float& tl, float& th, float& ul, float& uh)
{
    const float L2E = 1.4426950408889634f;
    const int bhs = hiv ? bh : bl;

    const float4* xiL = (const float4*)(inputs + (size_t)bl  * SEQ);
    const float4* xiH = (const float4*)(inputs + (size_t)bhs * SEQ);
    float4 a0 = xiL[0], a1 = xiL[1], a2 = xiL[2];
    float4 b0 = xiH[0], b1 = xiH[1], b2 = xiH[2];
    float xl[SEQ] = {a0.x,a0.y,a0.z,a0.w, a1.x,a1.y,a1.z,a1.w, a2.x,a2.y,a2.z,a2.w};
    float xh[SEQ] = {b0.x,b0.y,b0.z,b0.w, b1.x,b1.y,b1.z,b1.w, b2.x,b2.y,b2.z,b2.w};
    tl = targets[bl];
    th = targets[bhs];

    // scores + per-half max
    const float k0l = fmaf(A, tl, Bc), k0h = fmaf(A, th, Bc);
    const float k1l = fmaf(Cc, tl, Dc), k1h = fmaf(Cc, th, Dc);
    float scl[SEQ], sch[SEQ];
    #pragma unroll
    for (int s = 0; s < SEQ; s++)
        fma2(scl[s], sch[s], k0l, k0h, xl[s], xh[s], k1l, k1h);
    float ml = scl[0], mh = sch[0];
    #pragma unroll
    for (int s = 1; s < SEQ; s++) { ml = fmaxf(ml, scl[s]); mh = fmaxf(mh, sch[s]); }

    // pm = sc * (log2e/m); second max (m may be negative -> order flips, as in ref)
    const float iml = __fdividef(L2E, ml);
    const float imh = __fdividef(L2E, mh);
    float pml[SEQ], pmh[SEQ];
    #pragma unroll
    for (int s = 0; s < SEQ; s++)
        mul2(pml[s], pmh[s], scl[s], sch[s], iml, imh);
    float mpl = pml[0], mph = pmh[0];
    #pragma unroll
    for (int s = 1; s < SEQ; s++) { mpl = fmaxf(mpl, pml[s]); mph = fmaxf(mph, pmh[s]); }

    // exp, E, U
    const float nmpl = -mpl, nmph = -mph;
    float eel[SEQ], eeh[SEQ];
    float El = 0.f, Eh = 0.f, Ul = 0.f, Uh = 0.f;
    #pragma unroll
    for (int s = 0; s < SEQ; s++) {
        float dl, dh;
        add2(dl, dh, pml[s], pmh[s], nmpl, nmph);
        eel[s] = ex2a(dl);
        eeh[s] = ex2a(dh);
        add2(El, Eh, El, Eh, eel[s], eeh[s]);
        fma2(Ul, Uh, eel[s], eeh[s], xl[s], xh[s], Ul, Uh);
    }
    ul = Ul * __fdividef(1.0f, El);
    uh = Uh * __fdividef(1.0f, Eh);

    // mask: attn_s > mean(attn)  <=>  12*ee_s > E
    if (write_mask) {
        float ll[SEQ], hm[SEQ];
        #pragma unroll
        for (int s = 0; s < SEQ; s++) {
            ll[s] = (12.0f * eel[s] > El) ? 1.0f : 0.0f;
            hm[s] = (12.0f * eeh[s] > Eh) ? 1.0f : 0.0f;
        }
        float4* mo = (float4*)(out + B + (size_t)bl * SEQ);
        mo[0] = make_float4(ll[0], ll[1], ll[2],  ll[3]);
        mo[1] = make_float4(ll[4], ll[5], ll[6],  ll[7]);
        mo[2] = make_float4(ll[8], ll[9], ll[10], ll[11]);
        if (hiv) {
            float4* mo2 = (float4*)(out + B + (size_t)bh * SEQ);
            mo2[0] = make_float4(hm[0], hm[1], hm[2],  hm[3]);
            mo2[1] = make_float4(hm[4], hm[5], hm[6],  hm[7]);
            mo2[2] = make_float4(hm[8], hm[9], hm[10], hm[11]);
        }
    }
}

__global__ __launch_bounds__(TPB) void maskmodel_kernel(
    const float* __restrict__ inputs,   // [B, S, 1]
    const float* __restrict__ targets,  // [B, 1]
    const float* __restrict__ We_w, const float* __restrict__ We_b,
    const float* __restrict__ Wt_w, const float* __restrict__ Wt_b,
    const float* __restrict__ W1_w, const float* __restrict__ W1_b,
    const float* __restrict__ W2_w, const float* __restrict__ W2_b,
    const float* __restrict__ W3_w, const float* __restrict__ W3_b,
    float* __restrict__ out, int B, int write_mask)
{
    // broadcast-duplicated packed weights: each scalar stored twice so packed
    // operands come straight from LDS.64/LDS.128 (no pack MOVs in hot loop)
    __shared__ float4 sPQ[H1];            // {P,P,Q,Q}
    __shared__ float2 sRR[H1];            // {R,R}
    __shared__ float4 sW2q[H1][H2 / 2];   // {w_i,w_i,w_{i+1},w_{i+1}}, w_i = W2[i][j]
    __shared__ float  sW2b[H2], sW3[H2];
    __shared__ float  sK[5];              // A, Bc, C, Dc, W3_b

    const int tid = threadIdx.x;

    // ---- per-block derived-weight precompute (tiny, redundant per block) ----
    if (tid < H1) {
        float p = 0.f, q = 0.f, r = W1_b[tid];
        #pragma unroll
        for (int i = 0; i < DIM; i++) {
            float w1a = W1_w[tid * 2 * DIM + i];        // W1[j, i]
            float w1b = W1_w[tid * 2 * DIM + DIM + i];  // W1[j, 10+i]
            p = fmaf(w1a, Wt_w[i], p);
            q = fmaf(w1b, We_w[i], q);
            r = fmaf(w1a, Wt_b[i], fmaf(w1b, We_b[i], r));
        }
        sPQ[tid] = make_float4(p, p, q, q);
        sRR[tid] = make_float2(r, r);
    } else if (tid == H1) {
        float a = 0.f, bq = 0.f, c = 0.f, dd = 0.f;
        #pragma unroll
        for (int i = 0; i < DIM; i++) {
            a  = fmaf(We_w[i], Wt_w[i], a);
            bq = fmaf(We_w[i], Wt_b[i], bq);
            c  = fmaf(We_b[i], Wt_w[i], c);
            dd = fmaf(We_b[i], Wt_b[i], dd);
        }
        sK[0] = a; sK[1] = bq; sK[2] = c; sK[3] = dd; sK[4] = W3_b[0];
    }
    for (int k = tid; k < H1 * H2; k += TPB) {
        int j = k / H2, i = k % H2;
        float w = W2_w[i * H1 + j];                 // W2 is [10,50] row-major
        float* dst = (float*)&sW2q[j][i >> 1];
        dst[(i & 1) * 2 + 0] = w;
        dst[(i & 1) * 2 + 1] = w;
    }
    if (tid < H2) { sW2b[tid] = W2_b[tid]; sW3[tid] = W3_w[tid]; }
    __syncthreads();

    const float A  = sK[0], Bc = sK[1], Cc = sK[2], Dc = sK[3], W3b = sK[4];

    const int total = gridDim.x * TPB;             // elements per quarter
    const int b0 = blockIdx.x * TPB + tid;         // pair A lo
    if (b0 >= B) return;
    const int b1 = b0 + total;                     // pair A hi
    const int b2 = b0 + 2 * total;                 // pair B lo
    const int b3 = b0 + 3 * total;                 // pair B hi
    const bool v1 = (b1 < B), v2 = (b2 < B), v3 = (b3 < B);

    // ---- attention phases (sequential; arrays reused) ----
    float tAl, tAh, uAl, uAh;
    attn_phase(inputs, targets, out, B, write_mask, b0, b1, v1,
               A, Bc, Cc, Dc, tAl, tAh, uAl, uAh);
    float tBl = 0.f, tBh = 0.f, uBl = 0.f, uBh = 0.f;
    if (v2)
        attn_phase(inputs, targets, out, B, write_mask, b2, b3, v3,
                   A, Bc, Cc, Dc, tBl, tBh, uBl, uBh);

    // ---- fused h1 -> W2 hot loop: both pairs share every LDS broadcast ----
    float accAl[H2], accAh[H2], accBl[H2], accBh[H2];
    #pragma unroll
    for (int i = 0; i < H2; i++) {
        float wb = sW2b[i];
        accAl[i] = wb; accAh[i] = wb; accBl[i] = wb; accBh[i] = wb;
    }
    #pragma unroll 5
    for (int j = 0; j < H1; j++) {
        float4 pq = sPQ[j];                               // LDS.128 broadcast
        float2 rr = sRR[j];                               // LDS.64 broadcast
        float hAl, hAh, hBl, hBh;
        fma2(hAl, hAh, pq.z, pq.w, uAl, uAh, rr.x, rr.y); // Q*u + R
        fma2(hAl, hAh, pq.x, pq.y, tAl, tAh, hAl, hAh);   // + P*t
        fma2(hBl, hBh, pq.z, pq.w, uBl, uBh, rr.x, rr.y);
        fma2(hBl, hBh, pq.x, pq.y, tBl, tBh, hBl, hBh);
        hAl = fmaxf(hAl, 0.0f); hAh = fmaxf(hAh, 0.0f);
        hBl = fmaxf(hBl, 0.0f); hBh = fmaxf(hBh, 0.0f);
        #pragma unroll
        for (int q = 0; q < H2 / 2; q++) {
            float4 w = sW2q[j][q];                        // LDS.128 broadcast
            fma2(accAl[2*q],   accAh[2*q],   w.x, w.y, hAl, hAh, accAl[2*q],   accAh[2*q]);
            fma2(accAl[2*q+1], accAh[2*q+1], w.z, w.w, hAl, hAh, accAl[2*q+1], accAh[2*q+1]);
            fma2(accBl[2*q],   accBh[2*q],   w.x, w.y, hBl, hBh, accBl[2*q],   accBh[2*q]);
            fma2(accBl[2*q+1], accBh[2*q+1], w.z, w.w, hBl, hBh, accBl[2*q+1], accBh[2*q+1]);
        }
    }

    // ---- W3 ----
    float tmAl = W3b, tmAh = W3b, tmBl = W3b, tmBh = W3b;
    #pragma unroll
    for (int i = 0; i < H2; i++) {
        float w3 = sW3[i];
        fma2(tmAl, tmAh, w3, w3, fmaxf(accAl[i], 0.0f), fmaxf(accAh[i], 0.0f), tmAl, tmAh);
        fma2(tmBl, tmBh, w3, w3, fmaxf(accBl[i], 0.0f), fmaxf(accBh[i], 0.0f), tmBl, tmBh);
    }
    out[b0] = tmAl;
    if (v1) out[b1] = tmAh;
    if (v2) out[b2] = tmBl;
    if (v3) out[b3] = tmBh;
}

extern "C" void kernel_launch(void* const* d_in, const int* in_sizes, int n_in,
                              void* d_out, int out_size) {
    const float* inputs  = (const float*)d_in[0];
    const float* targets = (const float*)d_in[1];
    const float* We_w    = (const float*)d_in[2];
    const float* We_b    = (const float*)d_in[3];
    const float* Wt_w    = (const float*)d_in[4];
    const float* Wt_b    = (const float*)d_in[5];
    const float* W1_w    = (const float*)d_in[6];
    const float* W1_b    = (const float*)d_in[7];
    const float* W2_w    = (const float*)d_in[8];
    const float* W2_b    = (const float*)d_in[9];
    const float* W3_w    = (const float*)d_in[10];
    const float* W3_b    = (const float*)d_in[11];
    float* out = (float*)d_out;

    const int B = in_sizes[1];                       // targets is [B,1]
    const int write_mask = (out_size >= B * (1 + SEQ)) ? 1 : 0;
    const int blocks = (B + ELEMS * TPB - 1) / (ELEMS * TPB);

    maskmodel_kernel<<<blocks, TPB>>>(inputs, targets,
                                      We_w, We_b, Wt_w, Wt_b,
                                      W1_w, W1_b, W2_w, W2_b, W3_w, W3_b,
                                      out, B, write_mask);
}